// round 1
// baseline (speedup 1.0000x reference)
#include <cuda_runtime.h>
#include <cuda_bf16.h>

#define N_NODES 100000
#define SS 2
#define GG 8
#define E_EDGES 400000
#define MID 256
#define LL 4
#define IN_CH 265
#define M_ROWS (SS * N_NODES)   // 200000

#define BM 128
#define BN 128
#define BK 8
#define TM 8
#define TN 8

// ---------------- scratch (device globals: no allocation allowed) ----------------
__device__ float g_X0 [(size_t)M_ROWS * IN_CH];   // assembled input features
__device__ float g_XA [(size_t)M_ROWS * MID];
__device__ float g_XB [(size_t)M_ROWS * MID];
__device__ float g_AGG[(size_t)M_ROWS * MID];
__device__ int   g_deg_fwd[N_NODES],      g_deg_rev[N_NODES];
__device__ int   g_rowstart_fwd[N_NODES + 1], g_rowstart_rev[N_NODES + 1];
__device__ int   g_cursor_fwd[N_NODES],   g_cursor_rev[N_NODES];
__device__ float g_inv_fwd[N_NODES],      g_inv_rev[N_NODES];
__device__ int   g_csr_fwd[E_EDGES],      g_csr_rev[E_EDGES];
__device__ float g_out_acc[GG * SS];

__device__ __forceinline__ float* bufptr(int sel) {
    switch (sel) {
        case 0:  return g_X0;
        case 1:  return g_XA;
        case 2:  return g_XB;
        default: return g_AGG;
    }
}

// ---------------- zero counters ----------------
__global__ void k_zero() {
    int i = blockIdx.x * blockDim.x + threadIdx.x;
    if (i < N_NODES) { g_deg_fwd[i] = 0; g_deg_rev[i] = 0; }
    if (i < GG * SS) g_out_acc[i] = 0.f;
}

// ---------------- degrees ----------------
__global__ void k_deg(const int* __restrict__ ei) {
    int e = blockIdx.x * blockDim.x + threadIdx.x;
    if (e >= E_EDGES) return;
    atomicAdd(&g_deg_fwd[ei[E_EDGES + e]], 1);  // in-degree at tgt
    atomicAdd(&g_deg_rev[ei[e]], 1);            // out-degree at src
}

// ---------------- single-block exclusive scan -> rowstart/cursor/invdeg ----------------
__global__ void k_scan(int dir) {
    int*   deg      = dir ? g_deg_rev      : g_deg_fwd;
    int*   rowstart = dir ? g_rowstart_rev : g_rowstart_fwd;
    int*   cursor   = dir ? g_cursor_rev   : g_cursor_fwd;
    float* inv      = dir ? g_inv_rev      : g_inv_fwd;

    __shared__ int smv[1024];
    int t = threadIdx.x;
    const int CH = (N_NODES + 1023) / 1024;
    int beg = t * CH;
    int end = min(beg + CH, N_NODES);
    int local = 0;
    for (int i = beg; i < end; i++) local += deg[i];
    smv[t] = local;
    __syncthreads();
    for (int off = 1; off < 1024; off <<= 1) {
        int v = (t >= off) ? smv[t - off] : 0;
        __syncthreads();
        smv[t] += v;
        __syncthreads();
    }
    int run = (t == 0) ? 0 : smv[t - 1];
    for (int i = beg; i < end; i++) {
        int d = deg[i];
        rowstart[i] = run;
        cursor[i]   = run;
        inv[i]      = 1.0f / (float)(d > 0 ? d : 1);
        run += d;
    }
    if (t == 0) rowstart[N_NODES] = E_EDGES;
}

// ---------------- CSR fill ----------------
__global__ void k_fill(const int* __restrict__ ei) {
    int e = blockIdx.x * blockDim.x + threadIdx.x;
    if (e >= E_EDGES) return;
    int s = ei[e], t = ei[E_EDGES + e];
    g_csr_fwd[atomicAdd(&g_cursor_fwd[t], 1)] = s;
    g_csr_rev[atomicAdd(&g_cursor_rev[s], 1)] = t;
}

// ---------------- feature assembly: X0[s*N+n, 0..264] ----------------
__global__ void k_assemble(const float* __restrict__ x_feat,
                           const float* __restrict__ dim_feat,
                           const float* __restrict__ layout_feat,
                           const float* __restrict__ tile_feat,
                           const float* __restrict__ opcode_embed,
                           const int* __restrict__ node_opcode,
                           const int* __restrict__ batch) {
    int m = blockIdx.x;
    int s = m / N_NODES;
    int n = m - s * N_NODES;
    int opc = node_opcode[n];
    int g   = batch[n];
    float* dst = g_X0 + (size_t)m * IN_CH;
    for (int c = threadIdx.x; c < IN_CH; c += blockDim.x) {
        float v;
        if (c < 53)       v = x_feat[(size_t)n * 53 + c];
        else if (c < 85)  v = opcode_embed[opc * 32 + (c - 53)];
        else if (c < 223) v = dim_feat[(size_t)n * 138 + (c - 85)];
        else if (c < 247) v = layout_feat[((size_t)n * SS + s) * 24 + (c - 223)];
        else              v = tile_feat[((size_t)g * SS + s) * 18 + (c - 247)];
        dst[c] = v;
    }
}

// ---------------- CSR mean-aggregation (both S samples per block) ----------------
__global__ void k_aggregate(int xsel, int dir) {
    const float* X        = bufptr(xsel);
    const int*   rowstart = dir ? g_rowstart_rev : g_rowstart_fwd;
    const int*   csr      = dir ? g_csr_rev      : g_csr_fwd;
    const float* inv      = dir ? g_inv_rev      : g_inv_fwd;
    int n = blockIdx.x;
    int c = threadIdx.x;
    int beg = rowstart[n], end = rowstart[n + 1];
    float iv = inv[n];
    float acc0 = 0.f, acc1 = 0.f;
    for (int e = beg; e < end; e++) {
        int src = csr[e];
        acc0 += X[(size_t)src * MID + c];
        acc1 += X[((size_t)(N_NODES + src)) * MID + c];
    }
    g_AGG[(size_t)n * MID + c]              = acc0 * iv;
    g_AGG[(size_t)(N_NODES + n) * MID + c]  = acc1 * iv;
}

// ---------------- fused GEMM: C[:,cofs:cofs+NC] = relu(A1@W1 + A2@W2 + bias) ----------------
__global__ void __launch_bounds__(256, 2) k_gemm(
    int a1sel, int K1, const float* __restrict__ W1,
    int a2sel, int K2, const float* __restrict__ W2,
    const float* __restrict__ bias,
    int csel, int cofs, int NC)
{
    __shared__ __align__(16) float As[BK][BM];
    __shared__ __align__(16) float Bs[BK][BN];
    const int bm  = blockIdx.y * BM;
    const int bn  = blockIdx.x * BN;
    const int tid = threadIdx.x;
    const int tr  = (tid >> 4) * TM;
    const int tc  = (tid & 15) * TN;

    float acc[TM][TN];
    #pragma unroll
    for (int i = 0; i < TM; i++)
        #pragma unroll
        for (int j = 0; j < TN; j++) acc[i][j] = 0.f;

    #pragma unroll 1
    for (int seg = 0; seg < 2; seg++) {
        const float* A; const float* W; int K;
        if (seg == 0) { A = bufptr(a1sel); W = W1; K = K1; }
        else {
            if (a2sel < 0) break;
            A = bufptr(a2sel); W = W2; K = K2;
        }
        int ktiles = (K + BK - 1) / BK;
        #pragma unroll 1
        for (int kt = 0; kt < ktiles; kt++) {
            int k0 = kt * BK;
            #pragma unroll
            for (int i = 0; i < (BM * BK) / 256; i++) {
                int idx = tid + i * 256;
                int m = idx >> 3, k = idx & 7;
                int gm = bm + m, gk = k0 + k;
                As[k][m] = (gm < M_ROWS && gk < K) ? A[(size_t)gm * K + gk] : 0.f;
            }
            #pragma unroll
            for (int i = 0; i < (BK * BN) / 256; i++) {
                int idx = tid + i * 256;
                int k = idx >> 7, n = idx & 127;
                int gk = k0 + k;
                Bs[k][n] = (gk < K) ? W[(size_t)gk * NC + (bn + n)] : 0.f;
            }
            __syncthreads();
            #pragma unroll
            for (int kk = 0; kk < BK; kk++) {
                float4 a0 = *(const float4*)&As[kk][tr];
                float4 a1 = *(const float4*)&As[kk][tr + 4];
                float4 b0 = *(const float4*)&Bs[kk][tc];
                float4 b1 = *(const float4*)&Bs[kk][tc + 4];
                float a[TM] = {a0.x, a0.y, a0.z, a0.w, a1.x, a1.y, a1.z, a1.w};
                float b[TN] = {b0.x, b0.y, b0.z, b0.w, b1.x, b1.y, b1.z, b1.w};
                #pragma unroll
                for (int i = 0; i < TM; i++)
                    #pragma unroll
                    for (int j = 0; j < TN; j++)
                        acc[i][j] = fmaf(a[i], b[j], acc[i][j]);
            }
            __syncthreads();
        }
    }

    float* C = bufptr(csel) + cofs;
    #pragma unroll
    for (int i = 0; i < TM; i++) {
        int gm = bm + tr + i;
        if (gm >= M_ROWS) continue;
        #pragma unroll
        for (int j = 0; j < TN; j++) {
            int gn = bn + tc + j;
            float v = acc[i][j] + bias[gn];
            C[(size_t)gm * MID + gn] = fmaxf(v, 0.f);
        }
    }
}

// ---------------- head: pooled dot with headW slice, binned per (g,s) ----------------
__global__ void k_head(int xsel, const float* __restrict__ hW,
                       const int* __restrict__ batch) {
    const float* X = bufptr(xsel);
    __shared__ float bins[GG * SS];
    __shared__ float wsum[8];
    int tid = threadIdx.x;
    if (tid < GG * SS) bins[tid] = 0.f;
    float w = hW[tid];   // blockDim == MID == 256
    __syncthreads();
    for (int m = blockIdx.x; m < M_ROWS; m += gridDim.x) {
        int s = m / N_NODES;
        int n = m - s * N_NODES;
        float v = X[(size_t)m * MID + tid] * w;
        #pragma unroll
        for (int o = 16; o > 0; o >>= 1) v += __shfl_down_sync(0xffffffffu, v, o);
        if ((tid & 31) == 0) wsum[tid >> 5] = v;
        __syncthreads();
        if (tid == 0) {
            float t = 0.f;
            #pragma unroll
            for (int k = 0; k < 8; k++) t += wsum[k];
            bins[batch[n] * SS + s] += t;
        }
        __syncthreads();
    }
    if (tid < GG * SS) atomicAdd(&g_out_acc[tid], bins[tid]);
}

__global__ void k_out(float* __restrict__ out, const float* __restrict__ headb) {
    int i = threadIdx.x;
    if (i < GG * SS) out[i] = g_out_acc[i] + headb[0];
}

// ---------------- driver ----------------
extern "C" void kernel_launch(void* const* d_in, const int* in_sizes, int n_in,
                              void* d_out, int out_size) {
    const float* x_feat       = (const float*)d_in[0];
    const float* dim_feat     = (const float*)d_in[1];
    const float* layout_feat  = (const float*)d_in[2];
    const float* tile_feat    = (const float*)d_in[3];
    const float* opcode_embed = (const float*)d_in[4];
    const float* preW         = (const float*)d_in[5];
    const float* preb         = (const float*)d_in[6];
    const float* convWl       = (const float*)d_in[7];
    const float* convWr       = (const float*)d_in[8];
    const float* convb        = (const float*)d_in[9];
    const float* revWl        = (const float*)d_in[10];
    const float* revWr        = (const float*)d_in[11];
    const float* revb         = (const float*)d_in[12];
    const float* headW        = (const float*)d_in[13];
    const float* headb        = (const float*)d_in[14];
    const int*   node_opcode  = (const int*)d_in[15];
    const int*   batch        = (const int*)d_in[16];
    const int*   edge_index   = (const int*)d_in[17];
    float* out = (float*)d_out;

    const int MT = (M_ROWS + BM - 1) / BM;   // 1563

    k_zero<<<(N_NODES + 255) / 256, 256>>>();
    k_deg <<<(E_EDGES + 255) / 256, 256>>>(edge_index);
    k_scan<<<1, 1024>>>(0);
    k_scan<<<1, 1024>>>(1);
    k_fill<<<(E_EDGES + 255) / 256, 256>>>(edge_index);

    k_assemble<<<M_ROWS, 256>>>(x_feat, dim_feat, layout_feat, tile_feat,
                                opcode_embed, node_opcode, batch);

    // pre-linear: XA = relu(X0 @ preW + preb)
    k_gemm<<<dim3(2, MT), 256>>>(0, IN_CH, preW, -1, 0, nullptr, preb, 1, 0, MID);

    const int WSZ = MID * (MID / 2);   // 32768 per layer
    for (int i = 0; i < LL; i++) {
        int insel  = (i % 2 == 0) ? 1 : 2;
        int outsel = (i % 2 == 0) ? 2 : 1;
        // forward SAGE: Xout[:,0:128] = relu(AGG_fwd@Wl + Xin@Wr + b)
        k_aggregate<<<N_NODES, 256>>>(insel, 0);
        k_gemm<<<dim3(1, MT), 256>>>(3, MID, convWl + i * WSZ,
                                     insel, MID, convWr + i * WSZ,
                                     convb + i * (MID / 2), outsel, 0, MID / 2);
        // reverse SAGE: Xout[:,128:256]
        k_aggregate<<<N_NODES, 256>>>(insel, 1);
        k_gemm<<<dim3(1, MT), 256>>>(3, MID, revWl + i * WSZ,
                                     insel, MID, revWr + i * WSZ,
                                     revb + i * (MID / 2), outsel, MID / 2, MID / 2);
        if (i >= LL - 2)
            k_head<<<1024, 256>>>(outsel, headW + (i - (LL - 2)) * MID, batch);
    }

    k_out<<<1, 32>>>(out, headb);
}

// round 13
// speedup vs baseline: 2.2449x; 2.2449x over previous
#include <cuda_runtime.h>
#include <cuda_bf16.h>
#include <cstdint>

#define N_NODES 100000
#define SS 2
#define GG 8
#define E_EDGES 400000
#define MID 256
#define LL 4
#define IN_CH 265
#define IN_STRIDE 288
#define M_ROWS (SS * N_NODES)            // 200000
#define MTILES ((M_ROWS + 127) / 128)    // 1563

#define NSB 98                           // scan blocks
#define PRE_KT 9                         // 288/32 k-tiles for pre GEMM
#define LAY_KT 16                        // 512/32 k-tiles for layer GEMM
#define NBTILES (2 * PRE_KT + 8 * LAY_KT)// 146 weight tiles

// B tile layout (packed bf16x2): [n=128][kpair stride 20 b32], real kp 0..15
#define B_STRIDE 20
#define NTILE_B32 (128 * B_STRIDE)       // 2560 u32 per tile
// A tile smem layout: [row=128][kpair stride 20 b32], real kp 0..15
#define A_STRIDE 20

// ---------------- device scratch (no allocation allowed) ----------------
__device__ float    g_X0 [(size_t)M_ROWS * IN_STRIDE];
__device__ float    g_XA [(size_t)M_ROWS * MID];
__device__ float    g_XB [(size_t)M_ROWS * MID];
__device__ float    g_AGG[(size_t)M_ROWS * MID];
__device__ uint32_t g_Bhi[(size_t)NBTILES * NTILE_B32];
__device__ uint32_t g_Blo[(size_t)NBTILES * NTILE_B32];
__device__ int   g_deg_fwd[N_NODES],      g_deg_rev[N_NODES];
__device__ int   g_rowstart_fwd[N_NODES + 1], g_rowstart_rev[N_NODES + 1];
__device__ int   g_cursor_fwd[N_NODES],   g_cursor_rev[N_NODES];
__device__ float g_inv_fwd[N_NODES],      g_inv_rev[N_NODES];
__device__ int   g_csr_fwd[E_EDGES],      g_csr_rev[E_EDGES];
__device__ int   g_bsum[2][NSB];
__device__ float g_out_acc[GG * SS];

__device__ __forceinline__ float* bufptr(int sel) {
    switch (sel) {
        case 0:  return g_X0;
        case 1:  return g_XA;
        case 2:  return g_XB;
        default: return g_AGG;
    }
}

// ---------------- helpers ----------------
__device__ __forceinline__ uint32_t pack_hi(float x, float y, uint32_t& lo_out) {
    __nv_bfloat16 hx = __float2bfloat16(x);
    __nv_bfloat16 hy = __float2bfloat16(y);
    __nv_bfloat16 lx = __float2bfloat16(x - __bfloat162float(hx));
    __nv_bfloat16 ly = __float2bfloat16(y - __bfloat162float(hy));
    lo_out = ((uint32_t)__bfloat16_as_ushort(ly) << 16) | __bfloat16_as_ushort(lx);
    return ((uint32_t)__bfloat16_as_ushort(hy) << 16) | __bfloat16_as_ushort(hx);
}

__device__ __forceinline__ void mma_bf16(float* d, const uint32_t* a,
                                         uint32_t b0, uint32_t b1) {
    asm volatile(
        "mma.sync.aligned.m16n8k16.row.col.f32.bf16.bf16.f32 "
        "{%0,%1,%2,%3}, {%4,%5,%6,%7}, {%8,%9}, {%0,%1,%2,%3};"
        : "+f"(d[0]), "+f"(d[1]), "+f"(d[2]), "+f"(d[3])
        : "r"(a[0]), "r"(a[1]), "r"(a[2]), "r"(a[3]), "r"(b0), "r"(b1));
}

// ---------------- graph preprocessing ----------------
__global__ void k_zero() {
    int i = blockIdx.x * blockDim.x + threadIdx.x;
    if (i < N_NODES) { g_deg_fwd[i] = 0; g_deg_rev[i] = 0; }
    if (i < GG * SS) g_out_acc[i] = 0.f;
}

__global__ void k_deg(const int* __restrict__ ei) {
    int e = blockIdx.x * blockDim.x + threadIdx.x;
    if (e >= E_EDGES) return;
    atomicAdd(&g_deg_fwd[ei[E_EDGES + e]], 1);
    atomicAdd(&g_deg_rev[ei[e]], 1);
}

__global__ void k_blocksum() {
    __shared__ int sh[256];
    int dir = blockIdx.y;
    const int* deg = dir ? g_deg_rev : g_deg_fwd;
    int base = blockIdx.x * 1024 + threadIdx.x * 4;
    int s = 0;
    #pragma unroll
    for (int j = 0; j < 4; j++) { int i = base + j; if (i < N_NODES) s += deg[i]; }
    sh[threadIdx.x] = s;
    __syncthreads();
    for (int off = 128; off > 0; off >>= 1) {
        if (threadIdx.x < off) sh[threadIdx.x] += sh[threadIdx.x + off];
        __syncthreads();
    }
    if (threadIdx.x == 0) g_bsum[dir][blockIdx.x] = sh[0];
}

__global__ void k_scanb() {
    int t = threadIdx.x;
    if (t < 2) {
        int run = 0;
        int* bs = g_bsum[t];
        for (int b = 0; b < NSB; b++) { int v = bs[b]; bs[b] = run; run += v; }
    }
    if (t == 0) { g_rowstart_fwd[N_NODES] = E_EDGES; g_rowstart_rev[N_NODES] = E_EDGES; }
}

__global__ void k_scatter() {
    __shared__ int sh[256];
    int dir = blockIdx.y;
    const int* deg = dir ? g_deg_rev : g_deg_fwd;
    int* rowstart  = dir ? g_rowstart_rev : g_rowstart_fwd;
    int* cursor    = dir ? g_cursor_rev   : g_cursor_fwd;
    float* inv     = dir ? g_inv_rev      : g_inv_fwd;
    int t = threadIdx.x;
    int base = blockIdx.x * 1024 + t * 4;
    int d[4]; int s = 0;
    #pragma unroll
    for (int j = 0; j < 4; j++) { int i = base + j; d[j] = (i < N_NODES) ? deg[i] : 0; s += d[j]; }
    sh[t] = s;
    __syncthreads();
    for (int off = 1; off < 256; off <<= 1) {
        int v = (t >= off) ? sh[t - off] : 0;
        __syncthreads();
        sh[t] += v;
        __syncthreads();
    }
    int run = g_bsum[dir][blockIdx.x] + sh[t] - s;
    #pragma unroll
    for (int j = 0; j < 4; j++) {
        int i = base + j;
        if (i < N_NODES) {
            rowstart[i] = run;
            cursor[i]   = run;
            inv[i]      = 1.0f / (float)(d[j] > 0 ? d[j] : 1);
            run += d[j];
        }
    }
}

__global__ void k_fill(const int* __restrict__ ei) {
    int e = blockIdx.x * blockDim.x + threadIdx.x;
    if (e >= E_EDGES) return;
    int s = ei[e], t = ei[E_EDGES + e];
    g_csr_fwd[atomicAdd(&g_cursor_fwd[t], 1)] = s;
    g_csr_rev[atomicAdd(&g_cursor_rev[s], 1)] = t;
}

// ---------------- feature assembly (stride-288, zero padded) ----------------
__global__ void k_assemble(const float* __restrict__ x_feat,
                           const float* __restrict__ dim_feat,
                           const float* __restrict__ layout_feat,
                           const float* __restrict__ tile_feat,
                           const float* __restrict__ opcode_embed,
                           const int* __restrict__ node_opcode,
                           const int* __restrict__ batch) {
    int m = blockIdx.x;
    int s = m / N_NODES;
    int n = m - s * N_NODES;
    int opc = node_opcode[n];
    int g   = batch[n];
    float* dst = g_X0 + (size_t)m * IN_STRIDE;
    for (int c = threadIdx.x; c < IN_STRIDE; c += blockDim.x) {
        float v;
        if (c < 53)       v = x_feat[(size_t)n * 53 + c];
        else if (c < 85)  v = opcode_embed[opc * 32 + (c - 53)];
        else if (c < 223) v = dim_feat[(size_t)n * 138 + (c - 85)];
        else if (c < 247) v = layout_feat[((size_t)n * SS + s) * 24 + (c - 223)];
        else if (c < 265) v = tile_feat[((size_t)g * SS + s) * 18 + (c - 247)];
        else              v = 0.f;
        dst[c] = v;
    }
}

// ---------------- weight prep: transpose + bf16 hi/lo split + pack ----------------
// tile = 128 n-channels x 32 k; packed as [n][kpair], kpair 0..15, stride 20
__global__ void k_prepB(const float* __restrict__ preW,
                        const float* __restrict__ convWl, const float* __restrict__ convWr,
                        const float* __restrict__ revWl,  const float* __restrict__ revWr) {
    int tile = blockIdx.x;
    uint32_t* hi = g_Bhi + (size_t)tile * NTILE_B32;
    uint32_t* lo = g_Blo + (size_t)tile * NTILE_B32;
    for (int idx = threadIdx.x; idx < 2048; idx += blockDim.x) {
        int n  = idx >> 4;     // 0..127 output channel within tile
        int kp = idx & 15;     // bf16x2 pair within k=32
        float w[2];
        #pragma unroll
        for (int h = 0; h < 2; h++) {
            int kl = kp * 2 + h;
            float v = 0.f;
            if (tile < 2 * PRE_KT) {
                int nt = tile / PRE_KT, kt = tile % PRE_KT;
                int k = kt * 32 + kl;
                if (k < IN_CH) v = preW[(size_t)k * MID + nt * 128 + n];
            } else {
                int t2 = tile - 2 * PRE_KT;
                int gi = t2 / LAY_KT, kt = t2 % LAY_KT;
                int i = gi >> 1, d = gi & 1;
                int k = kt * 32 + kl;
                const float* Wl = d ? revWl : convWl;
                const float* Wr = d ? revWr : convWr;
                v = (k < 256) ? Wl[(size_t)i * 32768 + (size_t)k * 128 + n]
                              : Wr[(size_t)i * 32768 + (size_t)(k - 256) * 128 + n];
            }
            w[h] = v;
        }
        uint32_t l;
        uint32_t hpack = pack_hi(w[0], w[1], l);
        hi[n * B_STRIDE + kp] = hpack;
        lo[n * B_STRIDE + kp] = l;
    }
}

// ---------------- CSR mean-aggregation ----------------
__global__ void k_aggregate(int xsel, int dir) {
    const float* X        = bufptr(xsel);
    const int*   rowstart = dir ? g_rowstart_rev : g_rowstart_fwd;
    const int*   csr      = dir ? g_csr_rev      : g_csr_fwd;
    const float* inv      = dir ? g_inv_rev      : g_inv_fwd;
    int n = blockIdx.x;
    int c = threadIdx.x;
    int beg = rowstart[n], end = rowstart[n + 1];
    float iv = inv[n];
    float acc0 = 0.f, acc1 = 0.f;
    for (int e = beg; e < end; e++) {
        int src = csr[e];
        acc0 += X[(size_t)src * MID + c];
        acc1 += X[((size_t)(N_NODES + src)) * MID + c];
    }
    g_AGG[(size_t)n * MID + c]             = acc0 * iv;
    g_AGG[(size_t)(N_NODES + n) * MID + c] = acc1 * iv;
}

// ---------------- mma.sync bf16 split GEMM ----------------
// C[:, cofs + bx*128 : +128] = relu( A(k-tiles) @ Bprepped + bias )
// block 128 threads = 4 warps, warp tile 64x64, block tile 128x128, BK=32
__global__ void __launch_bounds__(128) k_mgemm(
    int a1sel, int k1t, int a2sel, int astride,
    const float* __restrict__ bias, int csel, int cofs,
    int tb0, int nkt)
{
    __shared__ uint32_t sAh[128 * A_STRIDE];
    __shared__ uint32_t sAl[128 * A_STRIDE];
    __shared__ uint32_t sBh[NTILE_B32];
    __shared__ uint32_t sBl[NTILE_B32];

    const int tid  = threadIdx.x;
    const int warp = tid >> 5, lane = tid & 31;
    const int wm = (warp >> 1) * 64;      // warp m offset
    const int wn = (warp & 1) * 64;       // warp n offset
    const int lr = lane >> 2;             // 0..7
    const int lc = lane & 3;              // 0..3
    const int bm = blockIdx.y * 128;
    const int tb = tb0 + blockIdx.x * nkt;

    const float* A1 = bufptr(a1sel);
    const float* A2 = (a2sel >= 0) ? bufptr(a2sel) : A1;

    float acc[4][8][4];
    #pragma unroll
    for (int mf = 0; mf < 4; mf++)
        #pragma unroll
        for (int nf = 0; nf < 8; nf++)
            #pragma unroll
            for (int r = 0; r < 4; r++) acc[mf][nf][r] = 0.f;

    for (int kt = 0; kt < nkt; kt++) {
        const float* A = (kt < k1t) ? A1 : A2;
        int k0 = ((kt < k1t) ? kt : kt - k1t) * 32;

        // ---- load A tile 128x32 fp32 -> split bf16 hi/lo packed ----
        #pragma unroll
        for (int i = 0; i < 8; i++) {
            int idx = i * 128 + tid;              // 0..1023
            int row = idx >> 3, q = idx & 7;      // q = float4 index (k q*4..q*4+3)
            int gm = bm + row;
            float4 v = make_float4(0.f, 0.f, 0.f, 0.f);
            if (gm < M_ROWS) v = *(const float4*)(A + (size_t)gm * astride + k0 + q * 4);
            uint32_t l0, l1;
            uint32_t h0 = pack_hi(v.x, v.y, l0);
            uint32_t h1 = pack_hi(v.z, v.w, l1);
            int base = row * A_STRIDE + q * 2;
            sAh[base] = h0; sAh[base + 1] = h1;
            sAl[base] = l0; sAl[base + 1] = l1;
        }
        // ---- copy B tile (pre-packed, padded layout): 2560 u32 = 640 int4 ----
        {
            const int4* bh = (const int4*)(g_Bhi + (size_t)(tb + kt) * NTILE_B32);
            const int4* bl = (const int4*)(g_Blo + (size_t)(tb + kt) * NTILE_B32);
            int4* dh = (int4*)sBh;
            int4* dl = (int4*)sBl;
            #pragma unroll
            for (int i = 0; i < 5; i++) {
                dh[i * 128 + tid] = bh[i * 128 + tid];
                dl[i * 128 + tid] = bl[i * 128 + tid];
            }
        }
        __syncthreads();

        // ---- compute: 2 k16 steps ----
        #pragma unroll
        for (int ks = 0; ks < 2; ks++) {
            uint32_t ah[4][4], al[4][4];
            int kp = ks * 8 + lc;
            #pragma unroll
            for (int mf = 0; mf < 4; mf++) {
                int row = wm + mf * 16 + lr;
                ah[mf][0] = sAh[row * A_STRIDE + kp];
                ah[mf][1] = sAh[(row + 8) * A_STRIDE + kp];
                ah[mf][2] = sAh[row * A_STRIDE + kp + 4];
                ah[mf][3] = sAh[(row + 8) * A_STRIDE + kp + 4];
                al[mf][0] = sAl[row * A_STRIDE + kp];
                al[mf][1] = sAl[(row + 8) * A_STRIDE + kp];
                al[mf][2] = sAl[row * A_STRIDE + kp + 4];
                al[mf][3] = sAl[(row + 8) * A_STRIDE + kp + 4];
            }
            #pragma unroll
            for (int nf = 0; nf < 8; nf++) {
                int n = wn + nf * 8 + lr;
                uint32_t bh0 = sBh[n * B_STRIDE + kp];
                uint32_t bh1 = sBh[n * B_STRIDE + kp + 4];
                uint32_t bl0 = sBl[n * B_STRIDE + kp];
                uint32_t bl1 = sBl[n * B_STRIDE + kp + 4];
                #pragma unroll
                for (int mf = 0; mf < 4; mf++) {
                    mma_bf16(acc[mf][nf], ah[mf], bh0, bh1);
                    mma_bf16(acc[mf][nf], al[mf], bh0, bh1);
                    mma_bf16(acc[mf][nf], ah[mf], bl0, bl1);
                }
            }
        }
        __syncthreads();
    }

    // ---- epilogue: bias + relu + store ----
    float* C = bufptr(csel);
    #pragma unroll
    for (int mf = 0; mf < 4; mf++) {
        int r0 = bm + wm + mf * 16 + lr;
        int r1 = r0 + 8;
        #pragma unroll
        for (int nf = 0; nf < 8; nf++) {
            int bcol = blockIdx.x * 128 + wn + nf * 8 + lc * 2;
            float b0 = bias[bcol], b1 = bias[bcol + 1];
            int col = cofs + bcol;
            if (r0 < M_ROWS) {
                float2 v;
                v.x = fmaxf(acc[mf][nf][0] + b0, 0.f);
                v.y = fmaxf(acc[mf][nf][1] + b1, 0.f);
                *(float2*)(C + (size_t)r0 * MID + col) = v;
            }
            if (r1 < M_ROWS) {
                float2 v;
                v.x = fmaxf(acc[mf][nf][2] + b0, 0.f);
                v.y = fmaxf(acc[mf][nf][3] + b1, 0.f);
                *(float2*)(C + (size_t)r1 * MID + col) = v;
            }
        }
    }
}

// ---------------- head ----------------
__global__ void k_head(int xsel, const float* __restrict__ hW,
                       const int* __restrict__ batch) {
    const float* X = bufptr(xsel);
    __shared__ float bins[GG * SS];
    __shared__ float wsum[8];
    int tid = threadIdx.x;
    if (tid < GG * SS) bins[tid] = 0.f;
    float w = hW[tid];
    __syncthreads();
    for (int m = blockIdx.x; m < M_ROWS; m += gridDim.x) {
        int s = m / N_NODES;
        int n = m - s * N_NODES;
        float v = X[(size_t)m * MID + tid] * w;
        #pragma unroll
        for (int o = 16; o > 0; o >>= 1) v += __shfl_down_sync(0xffffffffu, v, o);
        if ((tid & 31) == 0) wsum[tid >> 5] = v;
        __syncthreads();
        if (tid == 0) {
            float t = 0.f;
            #pragma unroll
            for (int k = 0; k < 8; k++) t += wsum[k];
            bins[batch[n] * SS + s] += t;
        }
        __syncthreads();
    }
    if (tid < GG * SS) atomicAdd(&g_out_acc[tid], bins[tid]);
}

__global__ void k_out(float* __restrict__ out, const float* __restrict__ headb) {
    int i = threadIdx.x;
    if (i < GG * SS) out[i] = g_out_acc[i] + headb[0];
}

// ---------------- driver ----------------
extern "C" void kernel_launch(void* const* d_in, const int* in_sizes, int n_in,
                              void* d_out, int out_size) {
    const float* x_feat       = (const float*)d_in[0];
    const float* dim_feat     = (const float*)d_in[1];
    const float* layout_feat  = (const float*)d_in[2];
    const float* tile_feat    = (const float*)d_in[3];
    const float* opcode_embed = (const float*)d_in[4];
    const float* preW         = (const float*)d_in[5];
    const float* preb         = (const float*)d_in[6];
    const float* convWl       = (const float*)d_in[7];
    const float* convWr       = (const float*)d_in[8];
    const float* convb        = (const float*)d_in[9];
    const float* revWl        = (const float*)d_in[10];
    const float* revWr        = (const float*)d_in[11];
    const float* revb         = (const float*)d_in[12];
    const float* headW        = (const float*)d_in[13];
    const float* headb        = (const float*)d_in[14];
    const int*   node_opcode  = (const int*)d_in[15];
    const int*   batch        = (const int*)d_in[16];
    const int*   edge_index   = (const int*)d_in[17];
    float* out = (float*)d_out;

    // graph structure
    k_zero    <<<(N_NODES + 255) / 256, 256>>>();
    k_deg     <<<(E_EDGES + 255) / 256, 256>>>(edge_index);
    k_blocksum<<<dim3(NSB, 2), 256>>>();
    k_scanb   <<<1, 32>>>();
    k_scatter <<<dim3(NSB, 2), 256>>>();
    k_fill    <<<(E_EDGES + 255) / 256, 256>>>(edge_index);

    // features + weights
    k_assemble<<<M_ROWS, 288>>>(x_feat, dim_feat, layout_feat, tile_feat,
                                opcode_embed, node_opcode, batch);
    k_prepB<<<NBTILES, 256>>>(preW, convWl, convWr, revWl, revWr);

    // pre-linear: XA = relu(X0 @ preW + preb)   (2 n-tiles of 128)
    k_mgemm<<<dim3(2, MTILES), 128>>>(0, PRE_KT, -1, IN_STRIDE,
                                      preb, 1, 0, 0, PRE_KT);

    for (int i = 0; i < LL; i++) {
        int insel  = (i % 2 == 0) ? 1 : 2;
        int outsel = (i % 2 == 0) ? 2 : 1;
        // forward SAGE: Xout[:,0:128] = relu([AGG_fwd|Xin] @ [Wl;Wr] + b)
        k_aggregate<<<N_NODES, 256>>>(insel, 0);
        k_mgemm<<<dim3(1, MTILES), 128>>>(3, 8, insel, MID,
                                          convb + i * 128, outsel, 0,
                                          2 * PRE_KT + (i * 2 + 0) * LAY_KT, LAY_KT);
        // reverse SAGE: Xout[:,128:256]
        k_aggregate<<<N_NODES, 256>>>(insel, 1);
        k_mgemm<<<dim3(1, MTILES), 128>>>(3, 8, insel, MID,
                                          revb + i * 128, outsel, 128,
                                          2 * PRE_KT + (i * 2 + 1) * LAY_KT, LAY_KT);
        if (i >= LL - 2)
            k_head<<<1024, 256>>>(outsel, headW + (i - (LL - 2)) * MID, batch);
    }

    k_out<<<1, 32>>>(out, headb);
}

// round 15
// speedup vs baseline: 2.7798x; 1.2383x over previous
#include <cuda_runtime.h>
#include <cuda_bf16.h>
#include <cstdint>

#define N_NODES 100000
#define SS 2
#define GG 8
#define E_EDGES 400000
#define MID 256
#define LL 4
#define IN_CH 265
#define IN_STRIDE 288
#define M_ROWS (SS * N_NODES)            // 200000
#define MTILES ((M_ROWS + 127) / 128)    // 1563

#define NSB 98                           // scan blocks
#define PRE_KT 9                         // 288/32 k-tiles for pre GEMM
#define NBTILES (2 * PRE_KT + 16 * 8)    // 18 pre + 128 layer tiles = 146

// A/B smem tile layout: [row/n = 128][kpair stride 20 b32], real kp 0..15
#define B_STRIDE 20
#define NTILE_B32 (128 * B_STRIDE)       // 2560 u32 per tile
#define A_STRIDE 20

// ---------------- device scratch (no allocation allowed) ----------------
__device__ float    g_X0 [(size_t)M_ROWS * IN_STRIDE];
__device__ float    g_XA [(size_t)M_ROWS * MID];
__device__ float    g_XB [(size_t)M_ROWS * MID];
__device__ float    g_P  [(size_t)M_ROWS * 512];   // per-layer projections
__device__ uint32_t g_Bhi[(size_t)NBTILES * NTILE_B32];
__device__ uint32_t g_Blo[(size_t)NBTILES * NTILE_B32];
__device__ int   g_deg_fwd[N_NODES],      g_deg_rev[N_NODES];
__device__ int   g_rowstart_fwd[N_NODES + 1], g_rowstart_rev[N_NODES + 1];
__device__ int   g_cursor_fwd[N_NODES],   g_cursor_rev[N_NODES];
__device__ float g_inv_fwd[N_NODES],      g_inv_rev[N_NODES];
__device__ int   g_csr_fwd[E_EDGES],      g_csr_rev[E_EDGES];
__device__ int   g_bsum[2][NSB];
__device__ float g_out_acc[GG * SS];

__device__ __forceinline__ float* bufptr(int sel) {
    switch (sel) {
        case 0:  return g_X0;
        case 1:  return g_XA;
        case 2:  return g_XB;
        default: return g_P;
    }
}

// ---------------- helpers ----------------
__device__ __forceinline__ uint32_t pack_hi(float x, float y, uint32_t& lo_out) {
    __nv_bfloat16 hx = __float2bfloat16(x);
    __nv_bfloat16 hy = __float2bfloat16(y);
    __nv_bfloat16 lx = __float2bfloat16(x - __bfloat162float(hx));
    __nv_bfloat16 ly = __float2bfloat16(y - __bfloat162float(hy));
    lo_out = ((uint32_t)__bfloat16_as_ushort(ly) << 16) | __bfloat16_as_ushort(lx);
    return ((uint32_t)__bfloat16_as_ushort(hy) << 16) | __bfloat16_as_ushort(hx);
}

__device__ __forceinline__ void mma_bf16(float* d, const uint32_t* a,
                                         uint32_t b0, uint32_t b1) {
    asm volatile(
        "mma.sync.aligned.m16n8k16.row.col.f32.bf16.bf16.f32 "
        "{%0,%1,%2,%3}, {%4,%5,%6,%7}, {%8,%9}, {%0,%1,%2,%3};"
        : "+f"(d[0]), "+f"(d[1]), "+f"(d[2]), "+f"(d[3])
        : "r"(a[0]), "r"(a[1]), "r"(a[2]), "r"(a[3]), "r"(b0), "r"(b1));
}

// ---------------- graph preprocessing ----------------
__global__ void k_zero() {
    int i = blockIdx.x * blockDim.x + threadIdx.x;
    if (i < N_NODES) { g_deg_fwd[i] = 0; g_deg_rev[i] = 0; }
    if (i < GG * SS) g_out_acc[i] = 0.f;
}

__global__ void k_deg(const int* __restrict__ ei) {
    int e = blockIdx.x * blockDim.x + threadIdx.x;
    if (e >= E_EDGES) return;
    atomicAdd(&g_deg_fwd[ei[E_EDGES + e]], 1);
    atomicAdd(&g_deg_rev[ei[e]], 1);
}

__global__ void k_blocksum() {
    __shared__ int sh[256];
    int dir = blockIdx.y;
    const int* deg = dir ? g_deg_rev : g_deg_fwd;
    int base = blockIdx.x * 1024 + threadIdx.x * 4;
    int s = 0;
    #pragma unroll
    for (int j = 0; j < 4; j++) { int i = base + j; if (i < N_NODES) s += deg[i]; }
    sh[threadIdx.x] = s;
    __syncthreads();
    for (int off = 128; off > 0; off >>= 1) {
        if (threadIdx.x < off) sh[threadIdx.x] += sh[threadIdx.x + off];
        __syncthreads();
    }
    if (threadIdx.x == 0) g_bsum[dir][blockIdx.x] = sh[0];
}

__global__ void k_scanb() {
    int t = threadIdx.x;
    if (t < 2) {
        int run = 0;
        int* bs = g_bsum[t];
        for (int b = 0; b < NSB; b++) { int v = bs[b]; bs[b] = run; run += v; }
    }
    if (t == 0) { g_rowstart_fwd[N_NODES] = E_EDGES; g_rowstart_rev[N_NODES] = E_EDGES; }
}

__global__ void k_scatter() {
    __shared__ int sh[256];
    int dir = blockIdx.y;
    const int* deg = dir ? g_deg_rev : g_deg_fwd;
    int* rowstart  = dir ? g_rowstart_rev : g_rowstart_fwd;
    int* cursor    = dir ? g_cursor_rev   : g_cursor_fwd;
    float* inv     = dir ? g_inv_rev      : g_inv_fwd;
    int t = threadIdx.x;
    int base = blockIdx.x * 1024 + t * 4;
    int d[4]; int s = 0;
    #pragma unroll
    for (int j = 0; j < 4; j++) { int i = base + j; d[j] = (i < N_NODES) ? deg[i] : 0; s += d[j]; }
    sh[t] = s;
    __syncthreads();
    for (int off = 1; off < 256; off <<= 1) {
        int v = (t >= off) ? sh[t - off] : 0;
        __syncthreads();
        sh[t] += v;
        __syncthreads();
    }
    int run = g_bsum[dir][blockIdx.x] + sh[t] - s;
    #pragma unroll
    for (int j = 0; j < 4; j++) {
        int i = base + j;
        if (i < N_NODES) {
            rowstart[i] = run;
            cursor[i]   = run;
            inv[i]      = 1.0f / (float)(d[j] > 0 ? d[j] : 1);
            run += d[j];
        }
    }
}

__global__ void k_fill(const int* __restrict__ ei) {
    int e = blockIdx.x * blockDim.x + threadIdx.x;
    if (e >= E_EDGES) return;
    int s = ei[e], t = ei[E_EDGES + e];
    g_csr_fwd[atomicAdd(&g_cursor_fwd[t], 1)] = s;
    g_csr_rev[atomicAdd(&g_cursor_rev[s], 1)] = t;
}

// ---------------- feature assembly (stride-288, zero padded) ----------------
__global__ void k_assemble(const float* __restrict__ x_feat,
                           const float* __restrict__ dim_feat,
                           const float* __restrict__ layout_feat,
                           const float* __restrict__ tile_feat,
                           const float* __restrict__ opcode_embed,
                           const int* __restrict__ node_opcode,
                           const int* __restrict__ batch) {
    int m = blockIdx.x;
    int s = m / N_NODES;
    int n = m - s * N_NODES;
    int opc = node_opcode[n];
    int g   = batch[n];
    float* dst = g_X0 + (size_t)m * IN_STRIDE;
    for (int c = threadIdx.x; c < IN_STRIDE; c += blockDim.x) {
        float v;
        if (c < 53)       v = x_feat[(size_t)n * 53 + c];
        else if (c < 85)  v = opcode_embed[opc * 32 + (c - 53)];
        else if (c < 223) v = dim_feat[(size_t)n * 138 + (c - 85)];
        else if (c < 247) v = layout_feat[((size_t)n * SS + s) * 24 + (c - 223)];
        else if (c < 265) v = tile_feat[((size_t)g * SS + s) * 18 + (c - 247)];
        else              v = 0.f;
        dst[c] = v;
    }
}

// ---------------- weight prep: transpose + bf16 hi/lo split + pack ----------------
// pre tiles 0..17: tile = nt*9 + kt   (nt 0..1, kt 0..8), source preW
// layer tiles 18+: tile = 18 + i*32 + nt*8 + kt; nt: 0=convWl 1=convWr 2=revWl 3=revWr
__global__ void k_prepB(const float* __restrict__ preW,
                        const float* __restrict__ convWl, const float* __restrict__ convWr,
                        const float* __restrict__ revWl,  const float* __restrict__ revWr) {
    int tile = blockIdx.x;
    uint32_t* hi = g_Bhi + (size_t)tile * NTILE_B32;
    uint32_t* lo = g_Blo + (size_t)tile * NTILE_B32;
    for (int idx = threadIdx.x; idx < 2048; idx += blockDim.x) {
        int n  = idx >> 4;     // 0..127 output channel within tile
        int kp = idx & 15;     // bf16x2 pair within k=32
        float w[2];
        #pragma unroll
        for (int h = 0; h < 2; h++) {
            int kl = kp * 2 + h;
            float v = 0.f;
            if (tile < 2 * PRE_KT) {
                int nt = tile / PRE_KT, kt = tile % PRE_KT;
                int k = kt * 32 + kl;
                if (k < IN_CH) v = preW[(size_t)k * MID + nt * 128 + n];
            } else {
                int t2 = tile - 2 * PRE_KT;
                int i  = t2 / 32;
                int r  = t2 % 32;
                int nt = r / 8, kt = r % 8;
                int k = kt * 32 + kl;
                const float* W;
                if (nt == 0)      W = convWl;
                else if (nt == 1) W = convWr;
                else if (nt == 2) W = revWl;
                else              W = revWr;
                v = W[(size_t)i * 32768 + (size_t)k * 128 + n];
            }
            w[h] = v;
        }
        uint32_t l;
        uint32_t hpack = pack_hi(w[0], w[1], l);
        hi[n * B_STRIDE + kp] = hpack;
        lo[n * B_STRIDE + kp] = l;
    }
}

// ---------------- mma.sync bf16 split GEMM (single A source) ----------------
// C[:, bx*128 : +128] (row stride cstride) = A @ Bprepped [ + bias, relu if bias ]
// block 128 threads = 4 warps, warp tile 64x64, block tile 128x128, BK=32
__global__ void __launch_bounds__(128) k_mgemm(
    int asel, int astride,
    const float* __restrict__ bias,           // nullptr -> raw output (no relu)
    int csel, int cstride, int tb0, int nkt)
{
    __shared__ uint32_t sAh[128 * A_STRIDE];
    __shared__ uint32_t sAl[128 * A_STRIDE];
    __shared__ uint32_t sBh[NTILE_B32];
    __shared__ uint32_t sBl[NTILE_B32];

    const int tid  = threadIdx.x;
    const int warp = tid >> 5, lane = tid & 31;
    const int wm = (warp >> 1) * 64;
    const int wn = (warp & 1) * 64;
    const int lr = lane >> 2;
    const int lc = lane & 3;
    const int bm = blockIdx.y * 128;
    const int tb = tb0 + blockIdx.x * nkt;

    const float* A = bufptr(asel);

    float acc[4][8][4];
    #pragma unroll
    for (int mf = 0; mf < 4; mf++)
        #pragma unroll
        for (int nf = 0; nf < 8; nf++)
            #pragma unroll
            for (int r = 0; r < 4; r++) acc[mf][nf][r] = 0.f;

    for (int kt = 0; kt < nkt; kt++) {
        int k0 = kt * 32;

        // ---- load A tile 128x32 fp32 -> split bf16 hi/lo packed ----
        #pragma unroll
        for (int i = 0; i < 8; i++) {
            int idx = i * 128 + tid;
            int row = idx >> 3, q = idx & 7;
            int gm = bm + row;
            float4 v = make_float4(0.f, 0.f, 0.f, 0.f);
            if (gm < M_ROWS) v = *(const float4*)(A + (size_t)gm * astride + k0 + q * 4);
            uint32_t l0, l1;
            uint32_t h0 = pack_hi(v.x, v.y, l0);
            uint32_t h1 = pack_hi(v.z, v.w, l1);
            int base = row * A_STRIDE + q * 2;
            sAh[base] = h0; sAh[base + 1] = h1;
            sAl[base] = l0; sAl[base + 1] = l1;
        }
        // ---- copy B tile (pre-packed, padded layout): 2560 u32 = 640 int4 ----
        {
            const int4* bh = (const int4*)(g_Bhi + (size_t)(tb + kt) * NTILE_B32);
            const int4* bl = (const int4*)(g_Blo + (size_t)(tb + kt) * NTILE_B32);
            int4* dh = (int4*)sBh;
            int4* dl = (int4*)sBl;
            #pragma unroll
            for (int i = 0; i < 5; i++) {
                dh[i * 128 + tid] = bh[i * 128 + tid];
                dl[i * 128 + tid] = bl[i * 128 + tid];
            }
        }
        __syncthreads();

        // ---- compute: 2 k16 steps ----
        #pragma unroll
        for (int ks = 0; ks < 2; ks++) {
            uint32_t ah[4][4], al[4][4];
            int kp = ks * 8 + lc;
            #pragma unroll
            for (int mf = 0; mf < 4; mf++) {
                int row = wm + mf * 16 + lr;
                ah[mf][0] = sAh[row * A_STRIDE + kp];
                ah[mf][1] = sAh[(row + 8) * A_STRIDE + kp];
                ah[mf][2] = sAh[row * A_STRIDE + kp + 4];
                ah[mf][3] = sAh[(row + 8) * A_STRIDE + kp + 4];
                al[mf][0] = sAl[row * A_STRIDE + kp];
                al[mf][1] = sAl[(row + 8) * A_STRIDE + kp];
                al[mf][2] = sAl[row * A_STRIDE + kp + 4];
                al[mf][3] = sAl[(row + 8) * A_STRIDE + kp + 4];
            }
            #pragma unroll
            for (int nf = 0; nf < 8; nf++) {
                int n = wn + nf * 8 + lr;
                uint32_t bh0 = sBh[n * B_STRIDE + kp];
                uint32_t bh1 = sBh[n * B_STRIDE + kp + 4];
                uint32_t bl0 = sBl[n * B_STRIDE + kp];
                uint32_t bl1 = sBl[n * B_STRIDE + kp + 4];
                #pragma unroll
                for (int mf = 0; mf < 4; mf++) {
                    mma_bf16(acc[mf][nf], ah[mf], bh0, bh1);
                    mma_bf16(acc[mf][nf], al[mf], bh0, bh1);
                    mma_bf16(acc[mf][nf], ah[mf], bl0, bl1);
                }
            }
        }
        __syncthreads();
    }

    // ---- epilogue ----
    float* C = bufptr(csel);
    const bool dorelu = (bias != nullptr);
    #pragma unroll
    for (int mf = 0; mf < 4; mf++) {
        int r0 = bm + wm + mf * 16 + lr;
        int r1 = r0 + 8;
        #pragma unroll
        for (int nf = 0; nf < 8; nf++) {
            int bcol = blockIdx.x * 128 + wn + nf * 8 + lc * 2;
            float b0 = dorelu ? bias[bcol] : 0.f;
            float b1 = dorelu ? bias[bcol + 1] : 0.f;
            if (r0 < M_ROWS) {
                float2 v;
                v.x = acc[mf][nf][0] + b0;
                v.y = acc[mf][nf][1] + b1;
                if (dorelu) { v.x = fmaxf(v.x, 0.f); v.y = fmaxf(v.y, 0.f); }
                *(float2*)(C + (size_t)r0 * cstride + bcol) = v;
            }
            if (r1 < M_ROWS) {
                float2 v;
                v.x = acc[mf][nf][2] + b0;
                v.y = acc[mf][nf][3] + b1;
                if (dorelu) { v.x = fmaxf(v.x, 0.f); v.y = fmaxf(v.y, 0.f); }
                *(float2*)(C + (size_t)r1 * cstride + bcol) = v;
            }
        }
    }
}

// ---------------- fused aggregate + combine + relu ----------------
// P[m][512] = [Pl_f | Pr_f | Pl_r | Pr_r]
// O[n][c]       = relu(inv_f * sum_{j->n} Pl_f[j][c] + Pr_f[n][c] + bf[c])
// O[n][128+c]   = relu(inv_r * sum_{n->j} Pl_r[j][c] + Pr_r[n][c] + br[c])
__global__ void __launch_bounds__(128) k_combine(int osel,
                                                 const float* __restrict__ bf,
                                                 const float* __restrict__ br) {
    const float* __restrict__ P = g_P;
    float* O = bufptr(osel);
    int n = blockIdx.x, c = threadIdx.x;

    int fb = g_rowstart_fwd[n], fe = g_rowstart_fwd[n + 1];
    int rb = g_rowstart_rev[n], re = g_rowstart_rev[n + 1];

    float af0 = 0.f, af1 = 0.f, ar0 = 0.f, ar1 = 0.f;
    for (int e = fb; e < fe; e++) {
        int src = g_csr_fwd[e];
        af0 += P[(size_t)src * 512 + c];
        af1 += P[(size_t)(N_NODES + src) * 512 + c];
    }
    for (int e = rb; e < re; e++) {
        int src = g_csr_rev[e];
        ar0 += P[(size_t)src * 512 + 256 + c];
        ar1 += P[(size_t)(N_NODES + src) * 512 + 256 + c];
    }
    float invf = g_inv_fwd[n], invr = g_inv_rev[n];
    float bfc = bf[c], brc = br[c];

    float sf0 = P[(size_t)n * 512 + 128 + c];
    float sf1 = P[(size_t)(N_NODES + n) * 512 + 128 + c];
    float sr0 = P[(size_t)n * 512 + 384 + c];
    float sr1 = P[(size_t)(N_NODES + n) * 512 + 384 + c];

    O[(size_t)n * MID + c]                       = fmaxf(af0 * invf + sf0 + bfc, 0.f);
    O[(size_t)n * MID + 128 + c]                 = fmaxf(ar0 * invr + sr0 + brc, 0.f);
    O[(size_t)(N_NODES + n) * MID + c]           = fmaxf(af1 * invf + sf1 + bfc, 0.f);
    O[(size_t)(N_NODES + n) * MID + 128 + c]     = fmaxf(ar1 * invr + sr1 + brc, 0.f);
}

// ---------------- head ----------------
__global__ void k_head(int xsel, const float* __restrict__ hW,
                       const int* __restrict__ batch) {
    const float* X = bufptr(xsel);
    __shared__ float bins[GG * SS];
    __shared__ float wsum[8];
    int tid = threadIdx.x;
    if (tid < GG * SS) bins[tid] = 0.f;
    float w = hW[tid];
    __syncthreads();
    for (int m = blockIdx.x; m < M_ROWS; m += gridDim.x) {
        int s = m / N_NODES;
        int n = m - s * N_NODES;
        float v = X[(size_t)m * MID + tid] * w;
        #pragma unroll
        for (int o = 16; o > 0; o >>= 1) v += __shfl_down_sync(0xffffffffu, v, o);
        if ((tid & 31) == 0) wsum[tid >> 5] = v;
        __syncthreads();
        if (tid == 0) {
            float t = 0.f;
            #pragma unroll
            for (int k = 0; k < 8; k++) t += wsum[k];
            bins[batch[n] * SS + s] += t;
        }
        __syncthreads();
    }
    if (tid < GG * SS) atomicAdd(&g_out_acc[tid], bins[tid]);
}

__global__ void k_out(float* __restrict__ out, const float* __restrict__ headb) {
    int i = threadIdx.x;
    if (i < GG * SS) out[i] = g_out_acc[i] + headb[0];
}

// ---------------- driver ----------------
extern "C" void kernel_launch(void* const* d_in, const int* in_sizes, int n_in,
                              void* d_out, int out_size) {
    const float* x_feat       = (const float*)d_in[0];
    const float* dim_feat     = (const float*)d_in[1];
    const float* layout_feat  = (const float*)d_in[2];
    const float* tile_feat    = (const float*)d_in[3];
    const float* opcode_embed = (const float*)d_in[4];
    const float* preW         = (const float*)d_in[5];
    const float* preb         = (const float*)d_in[6];
    const float* convWl       = (const float*)d_in[7];
    const float* convWr       = (const float*)d_in[8];
    const float* convb        = (const float*)d_in[9];
    const float* revWl        = (const float*)d_in[10];
    const float* revWr        = (const float*)d_in[11];
    const float* revb         = (const float*)d_in[12];
    const float* headW        = (const float*)d_in[13];
    const float* headb        = (const float*)d_in[14];
    const int*   node_opcode  = (const int*)d_in[15];
    const int*   batch        = (const int*)d_in[16];
    const int*   edge_index   = (const int*)d_in[17];
    float* out = (float*)d_out;

    // graph structure
    k_zero    <<<(N_NODES + 255) / 256, 256>>>();
    k_deg     <<<(E_EDGES + 255) / 256, 256>>>(edge_index);
    k_blocksum<<<dim3(NSB, 2), 256>>>();
    k_scanb   <<<1, 32>>>();
    k_scatter <<<dim3(NSB, 2), 256>>>();
    k_fill    <<<(E_EDGES + 255) / 256, 256>>>(edge_index);

    // features + weights
    k_assemble<<<M_ROWS, 288>>>(x_feat, dim_feat, layout_feat, tile_feat,
                                opcode_embed, node_opcode, batch);
    k_prepB<<<NBTILES, 256>>>(preW, convWl, convWr, revWl, revWr);

    // pre-linear: XA = relu(X0 @ preW + preb)   (2 n-tiles of 128)
    k_mgemm<<<dim3(2, MTILES), 128>>>(0, IN_STRIDE, preb, 1, MID, 0, PRE_KT);

    for (int i = 0; i < LL; i++) {
        int insel  = (i % 2 == 0) ? 1 : 2;
        int outsel = (i % 2 == 0) ? 2 : 1;
        // P = X @ [Wl_f | Wr_f | Wl_r | Wr_r]   (4 n-tiles, raw output)
        k_mgemm<<<dim3(4, MTILES), 128>>>(insel, MID, nullptr, 3, 512,
                                          2 * PRE_KT + i * 32, 8);
        // fused gather + self + bias + relu -> X_next
        k_combine<<<N_NODES, 128>>>(outsel, convb + i * 128, revb + i * 128);
        if (i >= LL - 2)
            k_head<<<1024, 256>>>(outsel, headW + (i - (LL - 2)) * MID, batch);
    }

    k_out<<<1, 32>>>(out, headb);
}